// round 1
// baseline (speedup 1.0000x reference)
#include <cuda_runtime.h>
#include <cstdint>

// PairManifoldConstrainedHyperConnections
// x: [65536, 512] fp32.  Per pixel: RMSNorm -> 24 dots (pre 4, post 4, res 16)
// -> tanh -> sigmoid/sigmoid/sinkhorn(20) -> out [65536, 6, 4] fp32.
//
// Design: thread-per-pixel (2 px/thread), 256 threads/block, 512 px/block,
// 128 blocks. x staged via cp.async double buffer (chunks of 32 floats/px,
// 128B-line aligned & coalesced). Weights (24x512) staged once in SMEM,
// quad-major, read as warp-uniform broadcasts. Dots accumulated with
// fma.rn.f32x2 (packed fp32) on RAW x; the RMS scale s is applied to the 24
// scalar dot results (dot(xn,w) == s*dot(x,w)).

#define TPB 256
#define PX_PER_BLOCK 512
#define QPC 8          // float4 quads per chunk (32 floats)
#define NCHUNK 16      // 16 * 32 = 512 floats
#define PITCH 9        // float4 pitch per pixel row in SMEM (conflict-free)
#define NW 24          // 4 pre + 4 post + 16 res

typedef unsigned long long ull;

__device__ __forceinline__ ull fma2(ull a, ull b, ull c) {
    ull d;
    asm("fma.rn.f32x2 %0, %1, %2, %3;" : "=l"(d) : "l"(a), "l"(b), "l"(c));
    return d;
}
__device__ __forceinline__ float lo2(ull v) { return __uint_as_float((unsigned)(v & 0xffffffffull)); }
__device__ __forceinline__ float hi2(ull v) { return __uint_as_float((unsigned)(v >> 32)); }
__device__ __forceinline__ float tanh_a(float x) { float y; asm("tanh.approx.f32 %0, %1;" : "=f"(y) : "f"(x)); return y; }
__device__ __forceinline__ float rcp_a(float x)  { float y; asm("rcp.approx.f32 %0, %1;"  : "=f"(y) : "f"(x)); return y; }
__device__ __forceinline__ float ex2_a(float x)  { float y; asm("ex2.approx.f32 %0, %1;"  : "=f"(y) : "f"(x)); return y; }
__device__ __forceinline__ float exp_a(float x)  { return ex2_a(x * 1.4426950408889634f); }

__device__ __forceinline__ void cp16(uint32_t dst_smem, const void* src) {
    asm volatile("cp.async.ca.shared.global [%0], [%1], 16;" :: "r"(dst_smem), "l"(src) : "memory");
}

// Per-pixel epilogue: scale dots by RMS s, tanh, gate heads, sinkhorn(20), store.
__device__ __forceinline__ void epilogue(
    const ull* acc, ull ss,
    float a_pre, float a_post, float a_res,
    const float* bp, const float* bq, const float* br,
    float* __restrict__ o)
{
    float ssv = lo2(ss) + hi2(ss);
    float s = rsqrtf(ssv * (1.0f / 512.0f) + 1.1920929e-07f);

    float d[24];
#pragma unroll
    for (int j = 0; j < 24; j++) d[j] = (lo2(acc[j]) + hi2(acc[j])) * s;

    float4 o0, o1;
    float* po0 = (float*)&o0;
    float* po1 = (float*)&o1;
#pragma unroll
    for (int j = 0; j < 4; j++) {
        po0[j] =        rcp_a(1.0f + exp_a(-(a_pre  * tanh_a(d[j])     + bp[j])));
        po1[j] = 2.0f * rcp_a(1.0f + exp_a(-(a_post * tanh_a(d[4 + j]) + bq[j])));
    }

    float M[16];
#pragma unroll
    for (int k = 0; k < 16; k++) M[k] = exp_a(a_res * tanh_a(d[8 + k]) + br[k]);

#pragma unroll 1
    for (int it = 0; it < 20; it++) {
#pragma unroll
        for (int i = 0; i < 4; i++) {
            float r = rcp_a(M[i*4] + M[i*4+1] + M[i*4+2] + M[i*4+3]);
            M[i*4] *= r; M[i*4+1] *= r; M[i*4+2] *= r; M[i*4+3] *= r;
        }
#pragma unroll
        for (int j = 0; j < 4; j++) {
            float r = rcp_a(M[j] + M[4+j] + M[8+j] + M[12+j]);
            M[j] *= r; M[4+j] *= r; M[8+j] *= r; M[12+j] *= r;
        }
    }

    float4* o4 = (float4*)o;
    o4[0] = o0;
    o4[1] = o1;
#pragma unroll
    for (int i = 0; i < 4; i++)
        o4[2 + i] = make_float4(M[i*4], M[i*4+1], M[i*4+2], M[i*4+3]);
}

__global__ void __launch_bounds__(TPB, 1)
pmchc_kernel(const float4* __restrict__ x4,
             const float4* __restrict__ wpre,
             const float4* __restrict__ wpost,
             const float4* __restrict__ wres,
             const float* __restrict__ bpre,
             const float* __restrict__ bpost,
             const float* __restrict__ bres,
             const float* __restrict__ apre,
             const float* __restrict__ apost,
             const float* __restrict__ ares,
             float* __restrict__ out)
{
    extern __shared__ float4 smem[];
    float4* wsm  = smem;            // NW*128 = 3072 float4 (48 KB), layout [quad][j]
    float4* xbuf = smem + NW * 128; // 2 * 512 * PITCH float4 (144 KB)

    const int t = threadIdx.x;
    const int pxbase = blockIdx.x * PX_PER_BLOCK;
    const uint32_t sbase = (uint32_t)__cvta_generic_to_shared(xbuf);

    // ---- stage chunk 0 (each chunk: 512 px * 32 floats, 128B-coalesced) ----
    {
        const float4* g = x4 + (size_t)pxbase * 128;
        uint32_t d = sbase;
#pragma unroll
        for (int sI = 0; sI < 16; sI++) {
            int i = t + sI * 256;
            int p = i >> 3, q = i & 7;
            cp16(d + (uint32_t)(p * PITCH + q) * 16, g + (size_t)p * 128 + q);
        }
    }
    asm volatile("cp.async.commit_group;" ::: "memory");

    // ---- stage weights: wsm[quad*24 + j], rows: 0-3 pre, 4-7 post, 8-23 res ----
    for (int i = t; i < NW * 128; i += TPB) {
        int q = i / NW, j = i % NW;
        float4 v;
        if (j < 4)       v = wpre[j * 128 + q];
        else if (j < 8)  v = wpost[(j - 4) * 128 + q];
        else             v = wres[(j - 8) * 128 + q];
        wsm[q * NW + j] = v;
    }

    ull accA[24], accB[24], ssA = 0ull, ssB = 0ull;
#pragma unroll
    for (int j = 0; j < 24; j++) { accA[j] = 0ull; accB[j] = 0ull; }

    for (int c = 0; c < NCHUNK; c++) {
        if (c + 1 < NCHUNK) {
            const float4* g = x4 + (size_t)pxbase * 128 + (c + 1) * 8;
            uint32_t d = sbase + (uint32_t)(((c + 1) & 1) * 512 * PITCH) * 16;
#pragma unroll
            for (int sI = 0; sI < 16; sI++) {
                int i = t + sI * 256;
                int p = i >> 3, q = i & 7;
                cp16(d + (uint32_t)(p * PITCH + q) * 16, g + (size_t)p * 128 + q);
            }
            asm volatile("cp.async.commit_group;" ::: "memory");
            asm volatile("cp.async.wait_group 1;" ::: "memory");
        } else {
            asm volatile("cp.async.wait_group 0;" ::: "memory");
        }
        __syncthreads();

        const ulonglong2* xb = (const ulonglong2*)(xbuf + (c & 1) * 512 * PITCH);
#pragma unroll
        for (int q = 0; q < QPC; q++) {
            ulonglong2 a = xb[t * PITCH + q];
            ulonglong2 b = xb[(t + 256) * PITCH + q];
            ssA = fma2(a.x, a.x, ssA); ssA = fma2(a.y, a.y, ssA);
            ssB = fma2(b.x, b.x, ssB); ssB = fma2(b.y, b.y, ssB);
            const ulonglong2* w = (const ulonglong2*)(wsm + (c * QPC + q) * NW);
#pragma unroll
            for (int j = 0; j < 24; j++) {
                ulonglong2 wv = w[j];  // warp-uniform broadcast LDS
                accA[j] = fma2(a.x, wv.x, fma2(a.y, wv.y, accA[j]));
                accB[j] = fma2(b.x, wv.x, fma2(b.y, wv.y, accB[j]));
            }
        }
        __syncthreads();
    }

    // ---- epilogue ----
    const float a_pre = __ldg(apre), a_post = __ldg(apost), a_res = __ldg(ares);
    float bp[4], bq[4], br[16];
#pragma unroll
    for (int j = 0; j < 4; j++) { bp[j] = __ldg(bpre + j); bq[j] = __ldg(bpost + j); }
#pragma unroll
    for (int k = 0; k < 16; k++) br[k] = __ldg(bres + k);

    epilogue(accA, ssA, a_pre, a_post, a_res, bp, bq, br,
             out + (size_t)(pxbase + t) * 24);
    epilogue(accB, ssB, a_pre, a_post, a_res, bp, bq, br,
             out + (size_t)(pxbase + t + 256) * 24);
}

extern "C" void kernel_launch(void* const* d_in, const int* in_sizes, int n_in,
                              void* d_out, int out_size)
{
    const float4* x4    = (const float4*)d_in[0];
    const float4* wpre  = (const float4*)d_in[1];
    const float4* wpost = (const float4*)d_in[2];
    const float4* wres  = (const float4*)d_in[3];
    const float*  bpre  = (const float*)d_in[4];
    const float*  bpost = (const float*)d_in[5];
    const float*  bres  = (const float*)d_in[6];
    const float*  apre  = (const float*)d_in[7];
    const float*  apost = (const float*)d_in[8];
    const float*  ares  = (const float*)d_in[9];
    float* out = (float*)d_out;

    int px = in_sizes[0] / 512;          // 65536
    int blocks = px / PX_PER_BLOCK;      // 128

    size_t smem = (size_t)(NW * 128 + 2 * 512 * PITCH) * sizeof(float4); // 192 KB
    cudaFuncSetAttribute(pmchc_kernel, cudaFuncAttributeMaxDynamicSharedMemorySize, (int)smem);

    pmchc_kernel<<<blocks, TPB, smem>>>(x4, wpre, wpost, wres,
                                        bpre, bpost, bres,
                                        apre, apost, ares, out);
}